// round 12
// baseline (speedup 1.0000x reference)
#include <cuda_runtime.h>

// ---------------------------------------------------------------------------
// Triaffine: out[b,z,x,y] = sum_{i,k,j} xb[b,x,i] * z[b,z,k] * W[i,k,j] * yb[b,y,j]
// B=8, S=128, D=512; W: [513, 512, 513] fp32.
//
// 3-stage GEMM chain (fp32, packed f32x2 FMA):
//   stage1: T[(b,x), k, j'] = Xb[1024,528] @ Wp[528, 512*528]
//   stage2: Q[(b,x), k, y]  = T_p[512,528] @ Yb_b^T[528,128]   (1024 batches)
//   stage3: out[b,z,x,y]    = Z_b[128,512] @ Q_p[512,128]       (1024 batches)
// j and i padded 513 -> 528 (33 k-tiles of 16) so all tiles are guard-free.
// ---------------------------------------------------------------------------

#define J_PAD 528
#define N1    (512 * J_PAD)      // 270336, stage-1 N / T row length
#define KW    262656             // 512*513, weight (k,j) plane per i

// Scratch (device globals: allocation-free per harness rules)
__device__ float g_Xb[1024 * J_PAD];                       //   2.1 MB
__device__ float g_Yb[1024 * J_PAD];                       //   2.1 MB
__device__ float g_Wp[(size_t)J_PAD * N1];                 // 571   MB
__device__ float g_T [(size_t)1024 * 512 * J_PAD];         // 1.11  GB
__device__ float g_Q [(size_t)1024 * 512 * 128];           // 268   MB

// ---------------- packed f32x2 helpers ----------------
__device__ __forceinline__ unsigned long long dup2(float a) {
    unsigned long long r;
    asm("mov.b64 %0, {%1, %1};" : "=l"(r) : "f"(a));
    return r;
}
__device__ __forceinline__ void ffma2(unsigned long long& c,
                                      unsigned long long a,
                                      unsigned long long b) {
    asm("fma.rn.f32x2 %0, %1, %2, %0;" : "+l"(c) : "l"(a), "l"(b));
}
__device__ __forceinline__ float2 unpk(unsigned long long v) {
    float2 r;
    asm("mov.b64 {%0, %1}, %2;" : "=f"(r.x), "=f"(r.y) : "l"(v));
    return r;
}

// ---------------- prep kernels ----------------
__global__ void prep_xy(const float* __restrict__ x, const float* __restrict__ y) {
    int idx = blockIdx.x * 256 + threadIdx.x;
    if (idx >= 1024 * J_PAD) return;
    int m = idx / J_PAD;
    int j = idx - m * J_PAD;
    float vx, vy;
    if (j < 512)      { vx = x[m * 512 + j]; vy = y[m * 512 + j]; }
    else if (j == 512){ vx = 1.0f;           vy = 1.0f; }
    else              { vx = 0.0f;           vy = 0.0f; }
    g_Xb[idx] = vx;
    g_Yb[idx] = vy;
}

// Repack W [513,512,513] -> Wp [528, 512*528] (zero-padded): makes stage-1
// B-operand loads float4-aligned and guard-free.
__global__ void repack_w(const float* __restrict__ W) {
    int idx = blockIdx.x * 256 + threadIdx.x;   // total 528*270336 = 142,737,408
    int i = idx / N1;
    int r = idx - i * N1;
    int k = r / J_PAD;
    int j = r - k * J_PAD;
    float v = 0.0f;
    if (i < 513 && j < 513) v = W[(size_t)i * KW + k * 513 + j];
    g_Wp[idx] = v;
}

// ---------------- 128x128x16 microkernel (shared) ----------------
// As: duplicated-A ({a,a} u64) [16][128]; Bs: fp32 [16][128].
// Thread computes 8x8 tile at (m0, n0) via 32 f32x2 FMAs per k-step.
__device__ __forceinline__ void mma_tile(const unsigned long long (*As)[128],
                                         const float (*Bsr)[128],
                                         int m0, int n0,
                                         unsigned long long acc[8][4]) {
#pragma unroll
    for (int kk = 0; kk < 16; ++kk) {
        const ulonglong2* pA = reinterpret_cast<const ulonglong2*>(&As[kk][m0]);
        ulonglong2 a0 = pA[0], a1 = pA[1], a2 = pA[2], a3 = pA[3];
        const ulonglong2* pB = reinterpret_cast<const ulonglong2*>(&Bsr[kk][n0]);
        ulonglong2 b0 = pB[0], b1 = pB[1];
        unsigned long long a[8] = {a0.x, a0.y, a1.x, a1.y, a2.x, a2.y, a3.x, a3.y};
        unsigned long long b[4] = {b0.x, b0.y, b1.x, b1.y};
#pragma unroll
        for (int i = 0; i < 8; ++i)
#pragma unroll
            for (int q = 0; q < 4; ++q)
                ffma2(acc[i][q], a[i], b[q]);
    }
}

// ---------------- stage 1: T = Xb @ Wp ----------------
// M=1024, N=270336, K=528. Grid (2112, 8), 256 threads.
__global__ __launch_bounds__(256) void sgemm1() {
    __shared__ __align__(16) unsigned long long As2[2][16][128];  // 32 KB
    __shared__ __align__(16) float              Bs [2][16][128];  // 16 KB
    const int tid  = threadIdx.x;
    const int nblk = blockIdx.x * 128;
    const int mblk = blockIdx.y * 128;
    const int m0 = (tid & 15) * 8;
    const int n0 = (tid >> 4) * 8;
    const int am = tid >> 2,  ac = (tid & 3) * 4;   // A: rows am, am+64
    const int br = tid >> 5,  bc = (tid & 31) * 4;  // B: rows br, br+8

    // prologue: tile 0 -> buffer 0
#pragma unroll
    for (int s = 0; s < 2; ++s) {
        float4 ra = *reinterpret_cast<const float4*>(
            &g_Xb[(mblk + am + s * 64) * J_PAD + ac]);
        As2[0][ac + 0][am + s * 64] = dup2(ra.x);
        As2[0][ac + 1][am + s * 64] = dup2(ra.y);
        As2[0][ac + 2][am + s * 64] = dup2(ra.z);
        As2[0][ac + 3][am + s * 64] = dup2(ra.w);
        float4 rb = *reinterpret_cast<const float4*>(
            &g_Wp[(size_t)(br + s * 8) * N1 + nblk + bc]);
        *reinterpret_cast<float4*>(&Bs[0][br + s * 8][bc]) = rb;
    }
    __syncthreads();

    unsigned long long acc[8][4];
#pragma unroll
    for (int i = 0; i < 8; ++i)
#pragma unroll
        for (int q = 0; q < 4; ++q) acc[i][q] = 0ull;

    const int KT = J_PAD / 16;  // 33
    for (int kt = 0; kt < KT; ++kt) {
        const int cur = kt & 1;
        float4 pa0, pa1, pb0, pb1;
        const bool pre = (kt + 1 < KT);
        if (pre) {
            pa0 = *reinterpret_cast<const float4*>(
                &g_Xb[(mblk + am) * J_PAD + (kt + 1) * 16 + ac]);
            pa1 = *reinterpret_cast<const float4*>(
                &g_Xb[(mblk + am + 64) * J_PAD + (kt + 1) * 16 + ac]);
            pb0 = *reinterpret_cast<const float4*>(
                &g_Wp[(size_t)((kt + 1) * 16 + br) * N1 + nblk + bc]);
            pb1 = *reinterpret_cast<const float4*>(
                &g_Wp[(size_t)((kt + 1) * 16 + br + 8) * N1 + nblk + bc]);
        }
        mma_tile(As2[cur], Bs[cur], m0, n0, acc);
        if (pre) {
            const int nx = cur ^ 1;
            As2[nx][ac + 0][am]      = dup2(pa0.x);
            As2[nx][ac + 1][am]      = dup2(pa0.y);
            As2[nx][ac + 2][am]      = dup2(pa0.z);
            As2[nx][ac + 3][am]      = dup2(pa0.w);
            As2[nx][ac + 0][am + 64] = dup2(pa1.x);
            As2[nx][ac + 1][am + 64] = dup2(pa1.y);
            As2[nx][ac + 2][am + 64] = dup2(pa1.z);
            As2[nx][ac + 3][am + 64] = dup2(pa1.w);
            *reinterpret_cast<float4*>(&Bs[nx][br][bc])     = pb0;
            *reinterpret_cast<float4*>(&Bs[nx][br + 8][bc]) = pb1;
        }
        __syncthreads();
    }

#pragma unroll
    for (int i = 0; i < 8; ++i) {
        float2 t0 = unpk(acc[i][0]), t1 = unpk(acc[i][1]);
        float2 t2 = unpk(acc[i][2]), t3 = unpk(acc[i][3]);
        float* dst = &g_T[(size_t)(mblk + m0 + i) * N1 + nblk + n0];
        *reinterpret_cast<float4*>(dst)     = make_float4(t0.x, t0.y, t1.x, t1.y);
        *reinterpret_cast<float4*>(dst + 4) = make_float4(t2.x, t2.y, t3.x, t3.y);
    }
}

// ---------------- stage 2: Q_p = T_p @ Yb_b^T ----------------
// Per batch p=(b,x): M=512(k), N=128(y), K=528(j). Grid (4, 1024).
__global__ __launch_bounds__(256) void sgemm2() {
    __shared__ __align__(16) unsigned long long As2[2][16][128];
    __shared__ __align__(16) float              Bs [2][16][128];
    const int tid  = threadIdx.x;
    const int mblk = blockIdx.x * 128;
    const int p    = blockIdx.y;
    const int b    = p >> 7;
    const float* Ap = &g_T [(size_t)p * 512 * J_PAD];
    const float* Bp = &g_Yb[(size_t)b * 128 * J_PAD];
    const int m0 = (tid & 15) * 8;
    const int n0 = (tid >> 4) * 8;
    const int am = tid >> 2, ac = (tid & 3) * 4;   // A rows am, am+64
    const int yv = tid >> 2, yc = (tid & 3) * 4;   // B (transposed): y rows yv, yv+64

#pragma unroll
    for (int s = 0; s < 2; ++s) {
        float4 ra = *reinterpret_cast<const float4*>(
            &Ap[(mblk + am + s * 64) * J_PAD + ac]);
        As2[0][ac + 0][am + s * 64] = dup2(ra.x);
        As2[0][ac + 1][am + s * 64] = dup2(ra.y);
        As2[0][ac + 2][am + s * 64] = dup2(ra.z);
        As2[0][ac + 3][am + s * 64] = dup2(ra.w);
        float4 rb = *reinterpret_cast<const float4*>(
            &Bp[(yv + s * 64) * J_PAD + yc]);
        Bs[0][yc + 0][yv + s * 64] = rb.x;
        Bs[0][yc + 1][yv + s * 64] = rb.y;
        Bs[0][yc + 2][yv + s * 64] = rb.z;
        Bs[0][yc + 3][yv + s * 64] = rb.w;
    }
    __syncthreads();

    unsigned long long acc[8][4];
#pragma unroll
    for (int i = 0; i < 8; ++i)
#pragma unroll
        for (int q = 0; q < 4; ++q) acc[i][q] = 0ull;

    const int KT = J_PAD / 16;  // 33
    for (int kt = 0; kt < KT; ++kt) {
        const int cur = kt & 1;
        float4 pa0, pa1, pb0, pb1;
        const bool pre = (kt + 1 < KT);
        if (pre) {
            pa0 = *reinterpret_cast<const float4*>(
                &Ap[(mblk + am) * J_PAD + (kt + 1) * 16 + ac]);
            pa1 = *reinterpret_cast<const float4*>(
                &Ap[(mblk + am + 64) * J_PAD + (kt + 1) * 16 + ac]);
            pb0 = *reinterpret_cast<const float4*>(
                &Bp[yv * J_PAD + (kt + 1) * 16 + yc]);
            pb1 = *reinterpret_cast<const float4*>(
                &Bp[(yv + 64) * J_PAD + (kt + 1) * 16 + yc]);
        }
        mma_tile(As2[cur], Bs[cur], m0, n0, acc);
        if (pre) {
            const int nx = cur ^ 1;
            As2[nx][ac + 0][am]      = dup2(pa0.x);
            As2[nx][ac + 1][am]      = dup2(pa0.y);
            As2[nx][ac + 2][am]      = dup2(pa0.z);
            As2[nx][ac + 3][am]      = dup2(pa0.w);
            As2[nx][ac + 0][am + 64] = dup2(pa1.x);
            As2[nx][ac + 1][am + 64] = dup2(pa1.y);
            As2[nx][ac + 2][am + 64] = dup2(pa1.z);
            As2[nx][ac + 3][am + 64] = dup2(pa1.w);
            Bs[nx][yc + 0][yv]      = pb0.x;
            Bs[nx][yc + 1][yv]      = pb0.y;
            Bs[nx][yc + 2][yv]      = pb0.z;
            Bs[nx][yc + 3][yv]      = pb0.w;
            Bs[nx][yc + 0][yv + 64] = pb1.x;
            Bs[nx][yc + 1][yv + 64] = pb1.y;
            Bs[nx][yc + 2][yv + 64] = pb1.z;
            Bs[nx][yc + 3][yv + 64] = pb1.w;
        }
        __syncthreads();
    }

#pragma unroll
    for (int i = 0; i < 8; ++i) {
        float2 t0 = unpk(acc[i][0]), t1 = unpk(acc[i][1]);
        float2 t2 = unpk(acc[i][2]), t3 = unpk(acc[i][3]);
        float* dst = &g_Q[(size_t)p * 512 * 128 +
                          (size_t)(mblk + m0 + i) * 128 + n0];
        *reinterpret_cast<float4*>(dst)     = make_float4(t0.x, t0.y, t1.x, t1.y);
        *reinterpret_cast<float4*>(dst + 4) = make_float4(t2.x, t2.y, t3.x, t3.y);
    }
}

// ---------------- stage 3: out_bx = Z_b @ Q_p ----------------
// Per batch p=(b,x): M=128(z), N=128(y), K=512. Grid (1024).
__global__ __launch_bounds__(256) void sgemm3(const float* __restrict__ Z,
                                              float* __restrict__ Out) {
    __shared__ __align__(16) unsigned long long As2[2][16][128];
    __shared__ __align__(16) float              Bs [2][16][128];
    const int tid = threadIdx.x;
    const int p   = blockIdx.x;
    const int b   = p >> 7;
    const int x   = p & 127;
    const float* Ap = Z   + (size_t)b * 128 * 512;
    const float* Bp = &g_Q[(size_t)p * 512 * 128];
    float* Cp = Out + (size_t)b * 2097152 + (size_t)x * 128;
    const int m0 = (tid & 15) * 8;
    const int n0 = (tid >> 4) * 8;
    const int am = tid >> 2,  ac = (tid & 3) * 4;
    const int br = tid >> 5,  bc = (tid & 31) * 4;

#pragma unroll
    for (int s = 0; s < 2; ++s) {
        float4 ra = *reinterpret_cast<const float4*>(
            &Ap[(am + s * 64) * 512 + ac]);
        As2[0][ac + 0][am + s * 64] = dup2(ra.x);
        As2[0][ac + 1][am + s * 64] = dup2(ra.y);
        As2[0][ac + 2][am + s * 64] = dup2(ra.z);
        As2[0][ac + 3][am + s * 64] = dup2(ra.w);
        float4 rb = *reinterpret_cast<const float4*>(
            &Bp[(br + s * 8) * 128 + bc]);
        *reinterpret_cast<float4*>(&Bs[0][br + s * 8][bc]) = rb;
    }
    __syncthreads();

    unsigned long long acc[8][4];
#pragma unroll
    for (int i = 0; i < 8; ++i)
#pragma unroll
        for (int q = 0; q < 4; ++q) acc[i][q] = 0ull;

    const int KT = 512 / 16;  // 32
    for (int kt = 0; kt < KT; ++kt) {
        const int cur = kt & 1;
        float4 pa0, pa1, pb0, pb1;
        const bool pre = (kt + 1 < KT);
        if (pre) {
            pa0 = *reinterpret_cast<const float4*>(
                &Ap[am * 512 + (kt + 1) * 16 + ac]);
            pa1 = *reinterpret_cast<const float4*>(
                &Ap[(am + 64) * 512 + (kt + 1) * 16 + ac]);
            pb0 = *reinterpret_cast<const float4*>(
                &Bp[((kt + 1) * 16 + br) * 128 + bc]);
            pb1 = *reinterpret_cast<const float4*>(
                &Bp[((kt + 1) * 16 + br + 8) * 128 + bc]);
        }
        mma_tile(As2[cur], Bs[cur], m0, n0, acc);
        if (pre) {
            const int nx = cur ^ 1;
            As2[nx][ac + 0][am]      = dup2(pa0.x);
            As2[nx][ac + 1][am]      = dup2(pa0.y);
            As2[nx][ac + 2][am]      = dup2(pa0.z);
            As2[nx][ac + 3][am]      = dup2(pa0.w);
            As2[nx][ac + 0][am + 64] = dup2(pa1.x);
            As2[nx][ac + 1][am + 64] = dup2(pa1.y);
            As2[nx][ac + 2][am + 64] = dup2(pa1.z);
            As2[nx][ac + 3][am + 64] = dup2(pa1.w);
            *reinterpret_cast<float4*>(&Bs[nx][br][bc])     = pb0;
            *reinterpret_cast<float4*>(&Bs[nx][br + 8][bc]) = pb1;
        }
        __syncthreads();
    }

#pragma unroll
    for (int i = 0; i < 8; ++i) {
        float2 t0 = unpk(acc[i][0]), t1 = unpk(acc[i][1]);
        float2 t2 = unpk(acc[i][2]), t3 = unpk(acc[i][3]);
        float* dst = Cp + (size_t)(m0 + i) * 16384 + n0;
        *reinterpret_cast<float4*>(dst)     = make_float4(t0.x, t0.y, t1.x, t1.y);
        *reinterpret_cast<float4*>(dst + 4) = make_float4(t2.x, t2.y, t3.x, t3.y);
    }
}

// ---------------- launcher ----------------
extern "C" void kernel_launch(void* const* d_in, const int* in_sizes, int n_in,
                              void* d_out, int out_size) {
    // weight = the largest input; x, y, z = remaining three, in metadata order
    int wi = 0;
    for (int i = 1; i < n_in; ++i)
        if (in_sizes[i] > in_sizes[wi]) wi = i;
    const float* xyz[3] = {nullptr, nullptr, nullptr};
    int c = 0;
    for (int i = 0; i < n_in; ++i)
        if (i != wi && c < 3) xyz[c++] = (const float*)d_in[i];
    const float* x = xyz[0];
    const float* y = xyz[1];
    const float* z = xyz[2];
    const float* w = (const float*)d_in[wi];
    float* out = (float*)d_out;

    prep_xy<<<(1024 * J_PAD) / 256, 256>>>(x, y);
    repack_w<<<(int)(((size_t)J_PAD * N1) / 256), 256>>>(w);

    dim3 g1(N1 / 128, 1024 / 128);   // (2112, 8)
    sgemm1<<<g1, 256>>>();

    dim3 g2(512 / 128, 1024);        // (4, 1024)
    sgemm2<<<g2, 256>>>();

    sgemm3<<<1024, 256>>>(z, out);
}